// round 6
// baseline (speedup 1.0000x reference)
#include <cuda_runtime.h>

typedef unsigned long long ull;

// ---------------------------------------------------------------------------
// f32x2 packed helpers (ptxas never auto-fuses; must come from PTX)
// ---------------------------------------------------------------------------
__device__ __forceinline__ ull pack2(float x, float y) {
    ull r;
    asm("mov.b64 %0, {%1, %2};" : "=l"(r) : "f"(x), "f"(y));
    return r;
}
__device__ __forceinline__ ull fma2(ull a, ull b, ull c) {
    ull d;
    asm("fma.rn.f32x2 %0, %1, %2, %3;" : "=l"(d) : "l"(a), "l"(b), "l"(c));
    return d;
}

// ---------------------------------------------------------------------------
// Fused kernel. Phase A (cheap, ~0.5us, redundant per block): exploit circuit
// structure U = X*L*X*L with L = kron of four 2x2 M_i = RY(w1)*RZ(w0) (same
// weights in both reps) and X = CNOT(0,1). Fold head_w/head_b into two real
// symmetric quadratic forms, collapse onto the 81-coef tensor in the
// (c^2,cs,s^2) basis, transform per-axis to the (1,cos,sin) basis, store
// grouped for LDS.128. Phase B: 2 samples/thread, 4x fast sincos -> nested
// Horner with f32x2 packed FMAs, both outputs in one 64-bit lane.
// ---------------------------------------------------------------------------
__global__ void __launch_bounds__(256)
fused_kernel(const float4* __restrict__ x4,
             ull* __restrict__ out,
             const float* __restrict__ w,
             const float* __restrict__ hw,
             const float* __restrict__ hb,
             int B) {
    __shared__ float2 Am[4][2][2];     // per-wire 2x2 complex M_i
    __shared__ float2 Lm[16][16];      // L = kron(M_0..M_3)
    __shared__ float  Ur[16][16];
    __shared__ float  Ui[16][16];
    __shared__ float2 Ca[81];
    __shared__ float2 Cb[81];
    __shared__ ulonglong2 Cs[45];      // grouped/padded: 9 groups x 5 x 16B

    const int t = threadIdx.x;          // 0..255
    const int r = t >> 4, c = t & 15;

    // ---- issue x loads first: DRAM latency hides under Phase A
    const int i0 = blockIdx.x * 512 + t;
    const int i1 = i0 + 256;
    const float4 xa = (i0 < B) ? x4[i0] : make_float4(0.f, 0.f, 0.f, 0.f);
    const float4 xb = (i1 < B) ? x4[i1] : make_float4(0.f, 0.f, 0.f, 0.f);

    // ================= Phase A =================
    if (t < 81) Ca[t] = make_float2(0.0f, 0.0f);
    if (t < 4) {
        float sz, cz, sy, cy;
        __sincosf(0.5f * w[t * 4 + 0], &sz, &cz);   // RZ angle
        __sincosf(0.5f * w[t * 4 + 1], &sy, &cy);   // RY angle
        // M = RY * RZ, with e = e^{-i th/2} = cz - i sz:
        //   [ cy*e   -sy*e* ]
        //   [ sy*e    cy*e* ]
        Am[t][0][0] = make_float2( cy * cz, -cy * sz);
        Am[t][0][1] = make_float2(-sy * cz, -sy * sz);
        Am[t][1][0] = make_float2( sy * cz, -sy * sz);
        Am[t][1][1] = make_float2( cy * cz,  cy * sz);
    }
    __syncthreads();

    // L[r][c] = prod_i M_i[r_i][c_i], wire i <-> bit (3-i)
    {
        float2 p = Am[0][(r >> 3) & 1][(c >> 3) & 1];
        #pragma unroll
        for (int i = 1; i < 4; ++i) {
            const float2 q = Am[i][(r >> (3 - i)) & 1][(c >> (3 - i)) & 1];
            p = make_float2(p.x * q.x - p.y * q.y, p.x * q.y + p.y * q.x);
        }
        Lm[r][c] = p;
    }
    __syncthreads();

    // U = X L X L:  U[r,c] = sum_k L[x(r)][x(k)] * L[k][c],
    // x(v) = v^4 if bit8 set (CNOT: control wire0/bit8, target wire1/bit4)
    {
        const int xr = (r & 8) ? (r ^ 4) : r;
        float ar = 0.0f, ai = 0.0f;
        #pragma unroll
        for (int k = 0; k < 16; ++k) {
            const int xk = (k & 8) ? (k ^ 4) : k;
            const float2 u = Lm[xr][xk];
            const float2 v = Lm[k][c];
            ar += u.x * v.x - u.y * v.y;
            ai += u.x * v.y + u.y * v.x;
        }
        Ur[r][c] = ar;
        Ui[r][c] = ai;
    }
    __syncthreads();

    // Quadratic forms: H_j[k][m] = sum_row c_j[row] Re(conj(U[row,k])U[row,m])
    // with bias folded onto the diagonal (sum of probs == 1).
    {
        const int k = r, m = c;
        float h0 = 0.0f, h1 = 0.0f;
        const float hw00 = hw[0], hw01 = hw[1], hw02 = hw[2], hw03 = hw[3];
        const float hw10 = hw[4], hw11 = hw[5], hw12 = hw[6], hw13 = hw[7];
        #pragma unroll
        for (int row = 0; row < 16; ++row) {
            const float s0 = (row & 8) ? -1.0f : 1.0f;
            const float s1 = (row & 4) ? -1.0f : 1.0f;
            const float s2 = (row & 2) ? -1.0f : 1.0f;
            const float s3 = (row & 1) ? -1.0f : 1.0f;
            const float zc0 = hw00 * s0 + hw01 * s1 + hw02 * s2 + hw03 * s3;
            const float zc1 = hw10 * s0 + hw11 * s1 + hw12 * s2 + hw13 * s3;
            const float ov = Ur[row][k] * Ur[row][m] + Ui[row][k] * Ui[row][m];
            h0 += zc0 * ov;
            h1 += zc1 * ov;
        }
        if (k == m) { h0 += hb[0]; h1 += hb[1]; }

        // (k,m) -> base-3 index in (c^2, cs, s^2) basis: digit = k_i + m_i
        int g = 0;
        #pragma unroll
        for (int i = 0; i < 4; ++i) {
            const int sh = 3 - i;
            g = g * 3 + (((k >> sh) & 1) + ((m >> sh) & 1));
        }
        atomicAdd(&Ca[g].x, h0);
        atomicAdd(&Ca[g].y, h1);
    }

    // Per-axis basis transform: (c^2, cs, s^2) -> (1, cos, sin)
    //   new[0] = .5*(old0+old2); new[1] = .5*(old0-old2); new[2] = .5*old1
    {
        float2* src = Ca;
        float2* dst = Cb;
        const int strides[4] = {27, 9, 3, 1};
        #pragma unroll 1
        for (int ax = 0; ax < 4; ++ax) {
            __syncthreads();
            if (t < 81) {
                const int st = strides[ax];
                const int pos = (t / st) % 3;
                const int base = t - pos * st;
                const float2 e0 = src[base];
                const float2 e1 = src[base + st];
                const float2 e2 = src[base + 2 * st];
                float2 o;
                if (pos == 0)      { o.x = 0.5f * (e0.x + e2.x); o.y = 0.5f * (e0.y + e2.y); }
                else if (pos == 1) { o.x = 0.5f * (e0.x - e2.x); o.y = 0.5f * (e0.y - e2.y); }
                else               { o.x = 0.5f * e1.x;          o.y = 0.5f * e1.y; }
                dst[t] = o;
            }
            float2* tmp = src; src = dst; dst = tmp;
        }
        __syncthreads();
        // 4 swaps -> result back in Ca (== src)

        // Grouped/padded layout: group g=(e0*3+e1), entries k=(e2*3+e3),
        // 20 floats per group (5 x 16B), pads zeroed.
        float* gp = reinterpret_cast<float*>(Cs);
        if (t < 81) {
            const int a  = t / 27;
            const int bq = (t / 9) % 3;
            const int k  = t % 9;
            const float2 v = src[t];
            const int off = (a * 3 + bq) * 20 + 2 * k;
            gp[off]     = v.x;
            gp[off + 1] = v.y;
        }
        if (t < 9) {
            gp[t * 20 + 18] = 0.0f;
            gp[t * 20 + 19] = 0.0f;
        }
        __syncthreads();
    }

    // ================= Phase B: 2 samples/thread =================
    ull pc[2][4], ps[2][4];   // [sample][axis], both halves identical
    {
        float sn, cn;
        #define DVQ_TRIG(S, XV)                                                              \
            __sincosf((XV).x, &sn, &cn); pc[S][0] = pack2(cn, cn); ps[S][0] = pack2(sn, sn); \
            __sincosf((XV).y, &sn, &cn); pc[S][1] = pack2(cn, cn); ps[S][1] = pack2(sn, sn); \
            __sincosf((XV).z, &sn, &cn); pc[S][2] = pack2(cn, cn); ps[S][2] = pack2(sn, sn); \
            __sincosf((XV).w, &sn, &cn); pc[S][3] = pack2(cn, cn); ps[S][3] = pack2(sn, sn);
        DVQ_TRIG(0, xa)
        DVQ_TRIG(1, xb)
        #undef DVQ_TRIG
    }

    ull F[2], Gc[2];
    #pragma unroll
    for (int a = 0; a < 3; ++a) {
        #pragma unroll
        for (int bq = 0; bq < 3; ++bq) {
            const int g = a * 3 + bq;
            const ulonglong2 q0 = Cs[g * 5 + 0];
            const ulonglong2 q1 = Cs[g * 5 + 1];
            const ulonglong2 q2 = Cs[g * 5 + 2];
            const ulonglong2 q3 = Cs[g * 5 + 3];
            const ulonglong2 q4 = Cs[g * 5 + 4];
            #pragma unroll
            for (int s = 0; s < 2; ++s) {
                // entries e0..e8 = (q0.x q0.y q1.x q1.y q2.x q2.y q3.x q3.y q4.x)
                ull t0 = fma2(pc[s][3], q0.y, q0.x);
                t0 = fma2(ps[s][3], q1.x, t0);
                ull t1 = fma2(pc[s][3], q2.x, q1.y);
                t1 = fma2(ps[s][3], q2.y, t1);
                ull t2 = fma2(pc[s][3], q3.y, q3.x);
                t2 = fma2(ps[s][3], q4.x, t2);
                const ull E = fma2(ps[s][2], t2, fma2(pc[s][2], t1, t0));
                if (bq == 0)      Gc[s] = E;
                else if (bq == 1) Gc[s] = fma2(pc[s][1], E, Gc[s]);
                else              Gc[s] = fma2(ps[s][1], E, Gc[s]);
            }
        }
        #pragma unroll
        for (int s = 0; s < 2; ++s) {
            if (a == 0)      F[s] = Gc[s];
            else if (a == 1) F[s] = fma2(pc[s][0], Gc[s], F[s]);
            else             F[s] = fma2(ps[s][0], Gc[s], F[s]);
        }
    }

    if (i0 < B) out[i0] = F[0];
    if (i1 < B) out[i1] = F[1];
}

extern "C" void kernel_launch(void* const* d_in, const int* in_sizes, int n_in,
                              void* d_out, int out_size) {
    const float* x  = (const float*)d_in[0];   // (B, 4) fp32
    const float* w  = (const float*)d_in[1];   // (2, 4, 4) fp32
    const float* hw = (const float*)d_in[2];   // (2, 4) fp32
    const float* hb = (const float*)d_in[3];   // (2,) fp32

    const int B = in_sizes[0] / 4;
    const int grid = (B + 511) / 512;          // 512 samples per block

    fused_kernel<<<grid, 256>>>((const float4*)x, (ull*)d_out, w, hw, hb, B);
}

// round 7
// speedup vs baseline: 1.9483x; 1.9483x over previous
#include <cuda_runtime.h>

typedef unsigned long long ull;

// ---------------------------------------------------------------------------
// f32x2 packed helpers (ptxas never auto-fuses; must come from PTX)
// ---------------------------------------------------------------------------
__device__ __forceinline__ ull pack2(float x, float y) {
    ull r;
    asm("mov.b64 %0, {%1, %2};" : "=l"(r) : "f"(x), "f"(y));
    return r;
}
__device__ __forceinline__ ull fma2(ull a, ull b, ull c) {
    ull d;
    asm("fma.rn.f32x2 %0, %1, %2, %3;" : "=l"(d) : "l"(a), "l"(b), "l"(c));
    return d;
}

// ---------------------------------------------------------------------------
// Structure: CNOT(0,1) only couples wires 0,1 -> circuit factorizes as
// (W on q0q1) x (V2 on q2) x (V3 on q3), with M_i = RY(w[i,1])*RZ(w[i,0]),
// W = (C*(M0 kron M1))^2, V_i = M_i^2.  Encoding state factorizes too, so
//   zexp_i (i=2,3) = a_i + b_i cos x_i + d_i sin x_i                (3 coefs)
//   zexp_j (j=0,1) = 9-coef form in (1,cos x0,sin x0)x(1,cos x1,sin x1)
// Fold head_w/head_b: per sample, out(j=0,1 packed in f32x2) =
//   Horner(T[3][3]) + B2*cos x2 + D2*sin x2 + B3*cos x3 + D3*sin x3
// -> 12 fma2 + 8 MUFU per sample, table entirely in registers.
// ---------------------------------------------------------------------------
__global__ void __launch_bounds__(256)
fused_kernel(const float4* __restrict__ x4,
             ull* __restrict__ out,
             const float* __restrict__ w,
             const float* __restrict__ hw,
             const float* __restrict__ hb,
             int B) {
    __shared__ float2 sM[4][4];    // per-wire 2x2 M_i, [i][r*2+c]
    __shared__ float2 sN[16];      // N = C*(M0 kron M1)  (4x4)
    __shared__ float2 sW[16];      // W = N*N
    __shared__ float  sG[2][16];   // G_j = Re(W^H Z_j W)
    __shared__ float  sS[2][3];    // singles (a,b,d) for wires 2,3
    __shared__ ull    sT[9];       // pair table, outputs packed (j0,j1)
    __shared__ ull    sU[4];       // B2, D2, B3, D3 packed

    const int t = threadIdx.x;

    // ---- issue x loads first: DRAM latency hides under Phase A
    const int i0 = blockIdx.x * 512 + t;
    const int i1 = i0 + 256;
    const float4 xa = (i0 < B) ? x4[i0] : make_float4(0.f, 0.f, 0.f, 0.f);
    const float4 xb = (i1 < B) ? x4[i1] : make_float4(0.f, 0.f, 0.f, 0.f);

    // ================= Phase A (tiny 4x4 algebra) =================
    if (t < 4) {
        float sz, cz, sy, cy;
        sincosf(0.5f * w[t * 4 + 0], &sz, &cz);   // RZ half-angle
        sincosf(0.5f * w[t * 4 + 1], &sy, &cy);   // RY half-angle
        // M = RY*RZ, e = cz - i sz:  [[cy*e, -sy*e*],[sy*e, cy*e*]]
        sM[t][0] = make_float2( cy * cz, -cy * sz);
        sM[t][1] = make_float2(-sy * cz, -sy * sz);
        sM[t][2] = make_float2( sy * cz, -sy * sz);
        sM[t][3] = make_float2( cy * cz,  cy * sz);
    }
    __syncthreads();

    if (t < 16) {
        // N[r][c] = (C * (M0 kron M1))[r][c]; CNOT permutes rows 2<->3.
        const int r = t >> 2, c = t & 3;
        const int rr = (r == 2) ? 3 : (r == 3) ? 2 : r;
        const float2 a = sM[0][(rr >> 1) * 2 + (c >> 1)];
        const float2 b = sM[1][(rr & 1) * 2 + (c & 1)];
        sN[t] = make_float2(a.x * b.x - a.y * b.y, a.x * b.y + a.y * b.x);
    } else if (t == 16 || t == 17) {
        // Singles: wire q = t-14 (2 or 3). V = M^2, P = V^H Z V.
        const float2* M = sM[t - 14];
        float2 V[4];
        #pragma unroll
        for (int r = 0; r < 2; ++r)
            #pragma unroll
            for (int c = 0; c < 2; ++c) {
                const float2 p = M[r * 2 + 0], q = M[0 * 2 + c];
                const float2 p2 = M[r * 2 + 1], q2 = M[1 * 2 + c];
                V[r * 2 + c] = make_float2(
                    p.x * q.x - p.y * q.y + p2.x * q2.x - p2.y * q2.y,
                    p.x * q.y + p.y * q.x + p2.x * q2.y + p2.y * q2.x);
            }
        const float p00 = V[0].x * V[0].x + V[0].y * V[0].y
                        - (V[2].x * V[2].x + V[2].y * V[2].y);
        const float p11 = V[1].x * V[1].x + V[1].y * V[1].y
                        - (V[3].x * V[3].x + V[3].y * V[3].y);
        const float rp01 = V[0].x * V[1].x + V[0].y * V[1].y
                         - (V[2].x * V[3].x + V[2].y * V[3].y);
        sS[t - 16][0] = 0.5f * (p00 + p11);   // a
        sS[t - 16][1] = 0.5f * (p00 - p11);   // b (cos coef)
        sS[t - 16][2] = rp01;                 // d (sin coef)
    }
    __syncthreads();

    if (t < 16) {
        // W = N * N (4x4 complex)
        const int r = t >> 2, c = t & 3;
        float ar = 0.0f, ai = 0.0f;
        #pragma unroll
        for (int k = 0; k < 4; ++k) {
            const float2 u = sN[r * 4 + k];
            const float2 v = sN[k * 4 + c];
            ar += u.x * v.x - u.y * v.y;
            ai += u.x * v.y + u.y * v.x;
        }
        sW[t] = make_float2(ar, ai);
    }
    __syncthreads();

    if (t < 32) {
        // G_j[k][m] = sum_r zsign_j(r) * Re(conj(W[r,k]) W[r,m])
        const int j = t >> 4, k = (t >> 2) & 3, m = t & 3;
        float g = 0.0f;
        #pragma unroll
        for (int r = 0; r < 4; ++r) {
            const float zs = (j == 0) ? ((r & 2) ? -1.0f : 1.0f)
                                      : ((r & 1) ? -1.0f : 1.0f);
            g += zs * (sW[r * 4 + k].x * sW[r * 4 + m].x +
                       sW[r * 4 + k].y * sW[r * 4 + m].y);
        }
        sG[j][k * 4 + m] = g;
    }
    __syncthreads();

    if (t < 9) {
        // T[e0][e1]: basis transform (c^2,cs,s^2)->(1,cos,sin) per axis.
        //   f(0,:)= (.5,.5,0); f(1,:)= (0,0,.5); f(2,:)= (.5,-.5,0)
        const float F[3][3] = {{0.5f, 0.5f, 0.0f},
                               {0.0f, 0.0f, 0.5f},
                               {0.5f, -0.5f, 0.0f}};
        const int e0 = t / 3, e1 = t % 3;
        const float hw00 = hw[0], hw01 = hw[1], hw10 = hw[4], hw11 = hw[5];
        float a0 = 0.0f, a1 = 0.0f;
        #pragma unroll
        for (int k = 0; k < 4; ++k)
            #pragma unroll
            for (int m = 0; m < 4; ++m) {
                const int d0 = (k >> 1) + (m >> 1);
                const int d1 = (k & 1) + (m & 1);
                const float ww = F[d0][e0] * F[d1][e1];
                const float g0 = sG[0][k * 4 + m];
                const float g1 = sG[1][k * 4 + m];
                a0 += ww * (hw00 * g0 + hw01 * g1);
                a1 += ww * (hw10 * g0 + hw11 * g1);
            }
        if (t == 0) {  // fold bias + singles' constant terms
            a0 += hb[0] + hw[2] * sS[0][0] + hw[3] * sS[1][0];
            a1 += hb[1] + hw[6] * sS[0][0] + hw[7] * sS[1][0];
        }
        sT[t] = pack2(a0, a1);
    } else if (t >= 9 && t < 13) {
        const int q = (t - 9) >> 1;       // 0 -> wire2, 1 -> wire3
        const int which = (t - 9) & 1;    // 0 -> b, 1 -> d
        const float v = sS[q][1 + which];
        sU[t - 9] = pack2(hw[2 + q] * v, hw[6 + q] * v);
    }
    __syncthreads();

    // ---- hoist table into registers (13 x b64, warp-uniform)
    const ull T00 = sT[0], T01 = sT[1], T02 = sT[2];
    const ull T10 = sT[3], T11 = sT[4], T12 = sT[5];
    const ull T20 = sT[6], T21 = sT[7], T22 = sT[8];
    const ull UB2 = sU[0], UD2 = sU[1], UB3 = sU[2], UD3 = sU[3];

    // ================= Phase B: 2 samples/thread =================
    #pragma unroll
    for (int s = 0; s < 2; ++s) {
        const float4 xv = s ? xb : xa;
        const int idx = s ? i1 : i0;

        float sn0, cn0, sn1, cn1, sn2, cn2, sn3, cn3;
        __sincosf(xv.x, &sn0, &cn0);    // full angles: basis is (1,cos,sin)
        __sincosf(xv.y, &sn1, &cn1);
        __sincosf(xv.z, &sn2, &cn2);
        __sincosf(xv.w, &sn3, &cn3);
        const ull pc0 = pack2(cn0, cn0), ps0 = pack2(sn0, sn0);
        const ull pc1 = pack2(cn1, cn1), ps1 = pack2(sn1, sn1);
        const ull pc2 = pack2(cn2, cn2), ps2 = pack2(sn2, sn2);
        const ull pc3 = pack2(cn3, cn3), ps3 = pack2(sn3, sn3);

        const ull e0 = fma2(ps1, T02, fma2(pc1, T01, T00));
        const ull e1 = fma2(ps1, T12, fma2(pc1, T11, T10));
        const ull e2 = fma2(ps1, T22, fma2(pc1, T21, T20));
        ull r = fma2(ps0, e2, fma2(pc0, e1, e0));
        r = fma2(pc2, UB2, r);
        r = fma2(ps2, UD2, r);
        r = fma2(pc3, UB3, r);
        r = fma2(ps3, UD3, r);

        if (idx < B) out[idx] = r;
    }
}

extern "C" void kernel_launch(void* const* d_in, const int* in_sizes, int n_in,
                              void* d_out, int out_size) {
    const float* x  = (const float*)d_in[0];   // (B, 4) fp32
    const float* w  = (const float*)d_in[1];   // (2, 4, 4) fp32
    const float* hw = (const float*)d_in[2];   // (2, 4) fp32
    const float* hb = (const float*)d_in[3];   // (2,) fp32

    const int B = in_sizes[0] / 4;
    const int grid = (B + 511) / 512;          // 512 samples per block

    fused_kernel<<<grid, 256>>>((const float4*)x, (ull*)d_out, w, hw, hb, B);
}